// round 14
// baseline (speedup 1.0000x reference)
#include <cuda_runtime.h>
#include <cuda_bf16.h>
#include <cuda_fp16.h>
#include <cstdint>

// ---------------------------------------------------------------------------
// GraphSAGE 3-layer forward, GB300 sm_103a (compute_103 PTX -> mma.sync/HMMA).
//   layer: out = h @ Ws + (segmean_dst h[src]) @ Wn + b  (+relu layers 0,1)
// R14 = R13 + chunked agg->gemm pipelining:
//   - nodes split into 2 tile-aligned chunks; agg chunks serial on stream A,
//     gemm chunks trail on stream B via per-chunk events -> gemm(c0) overlaps
//     agg(c1) (tensor-bound vs L2-bound, complementary pipes)
//   Core (R13): single-pass fp16 GEMM @ 3 CTA/SM, column-split persistent,
//   cp.async double-buffer, vectorized CSR on forked stream, 8-MLP agg.
// ---------------------------------------------------------------------------

#define DINL __device__ __forceinline__

constexpr int NODES_MAX = 100000;
constexpr int EDGES_MAX = 1600000;
constexpr int K_DIM = 128;
constexpr int WST = 136;                 // padded stride (fp16 elems) = 272B
constexpr int WPART = 256 * WST;         // weight image stride (elems)
constexpr int MT = 64;                   // GEMM row-tile

// scratch (__device__ globals; no allocs allowed)
__device__ int   g_deg[NODES_MAX];
__device__ int   g_roff[NODES_MAX];
__device__ int   g_cursor[NODES_MAX];
__device__ int   g_bsums[256];
__device__ int   g_csr[EDGES_MAX];
__device__ float g_inv[NODES_MAX];
__device__ __align__(16) float g_hs[(size_t)NODES_MAX * 128];
__device__ __align__(16) __half g_hn[(size_t)NODES_MAX * 128];
__device__ __align__(16) __half g_ah[(size_t)NODES_MAX * 128];
// per layer: single fp16 part = [N up to 256][WST] (N-major)
__device__ __align__(16) __half g_wpad[3][WPART];

// ---------------- helpers ----------------
DINL uint32_t smem_u32(const void* p) {
    uint32_t a;
    asm("{ .reg .u64 t; cvta.to.shared.u64 t, %1; cvt.u32.u64 %0, t; }"
        : "=r"(a) : "l"(p));
    return a;
}
DINL uint32_t pack_hf2(float a, float b) {
    __half2 t = __floats2half2_rn(a, b);
    return *(uint32_t*)&t;
}
DINL float2 hf2f(uint32_t u) {
    __half2 h = *reinterpret_cast<__half2*>(&u);
    return __half22float2(h);
}
DINL void mma_f16(float (&d)[4], uint32_t a0, uint32_t a1, uint32_t a2, uint32_t a3,
                  uint32_t b0, uint32_t b1) {
    asm volatile(
        "mma.sync.aligned.m16n8k16.row.col.f32.f16.f16.f32 "
        "{%0,%1,%2,%3}, {%4,%5,%6,%7}, {%8,%9}, {%0,%1,%2,%3};"
        : "+f"(d[0]), "+f"(d[1]), "+f"(d[2]), "+f"(d[3])
        : "r"(a0), "r"(a1), "r"(a2), "r"(a3), "r"(b0), "r"(b1));
}
DINL void ldsm_x4(uint32_t& r0, uint32_t& r1, uint32_t& r2, uint32_t& r3, uint32_t addr) {
    asm volatile("ldmatrix.sync.aligned.m8n8.x4.shared.b16 {%0,%1,%2,%3}, [%4];"
                 : "=r"(r0), "=r"(r1), "=r"(r2), "=r"(r3) : "r"(addr));
}
DINL void cp_async16(uint32_t saddr, const void* gptr, int sz) {
    asm volatile("cp.async.cg.shared.global [%0], [%1], 16, %2;"
                 :: "r"(saddr), "l"(gptr), "r"(sz));
}

template <int V>
DINL void vload(float (&v)[V], const float* p) {
    if constexpr (V == 4) {
        float4 t = *(const float4*)p;
        v[0] = t.x; v[1] = t.y; v[2] = t.z; v[3] = t.w;
    } else {
        float2 t = *(const float2*)p;
        v[0] = t.x; v[1] = t.y;
    }
}
template <int V>
DINL void hload(float (&v)[V], const __half* p) {
    if constexpr (V == 4) {
        uint2 u = *(const uint2*)p;
        float2 x = hf2f(u.x), y = hf2f(u.y);
        v[0] = x.x; v[1] = x.y; v[2] = y.x; v[3] = y.y;
    } else {
        uint32_t u = *(const uint32_t*)p;
        float2 x = hf2f(u);
        v[0] = x.x; v[1] = x.y;
    }
}

// ---------------- CSR build ----------------
__global__ void k_count(const int* __restrict__ dst, int E) {
    int i = blockIdx.x * 256 + threadIdx.x;
    int E4 = E >> 2;
    if (i < E4) {
        int4 d = *(const int4*)(dst + i * 4);
        atomicAdd(&g_deg[d.x], 1);
        atomicAdd(&g_deg[d.y], 1);
        atomicAdd(&g_deg[d.z], 1);
        atomicAdd(&g_deg[d.w], 1);
    }
    int t = E4 * 4 + i;
    if (t < E) atomicAdd(&g_deg[dst[t]], 1);
}

__global__ void k_scan1(int n) {
    __shared__ int sh[256];
    int t = threadIdx.x;
    int i0 = blockIdx.x * 1024 + t * 4;
    int v0 = (i0 + 0 < n) ? g_deg[i0 + 0] : 0;
    int v1 = (i0 + 1 < n) ? g_deg[i0 + 1] : 0;
    int v2 = (i0 + 2 < n) ? g_deg[i0 + 2] : 0;
    int v3 = (i0 + 3 < n) ? g_deg[i0 + 3] : 0;
    int p1 = v0, p2 = v0 + v1, p3 = p2 + v2, tot = p3 + v3;
    sh[t] = tot;
    __syncthreads();
    int incl = tot;
    for (int off = 1; off < 256; off <<= 1) {
        int x = (t >= off) ? sh[t - off] : 0;
        __syncthreads();
        incl += x;
        sh[t] = incl;
        __syncthreads();
    }
    int ex = incl - tot;
    if (i0 + 0 < n) g_roff[i0 + 0] = ex;
    if (i0 + 1 < n) g_roff[i0 + 1] = ex + p1;
    if (i0 + 2 < n) g_roff[i0 + 2] = ex + p2;
    if (i0 + 3 < n) g_roff[i0 + 3] = ex + p3;
    if (t == 255) g_bsums[blockIdx.x] = incl;
}

// merged scan2+scan3: every block redundantly scans g_bsums (nb <= 256)
__global__ void k_scan23(int n, int nb) {
    __shared__ int sh[256];
    __shared__ int ex[256];
    int t = threadIdx.x;
    int v = (t < nb) ? g_bsums[t] : 0;
    sh[t] = v;
    __syncthreads();
    int incl = v;
    for (int off = 1; off < 256; off <<= 1) {
        int x = (t >= off) ? sh[t - off] : 0;
        __syncthreads();
        incl += x;
        sh[t] = incl;
        __syncthreads();
    }
    ex[t] = incl - v;
    __syncthreads();
    int i = blockIdx.x * 256 + t;
    if (i >= n) return;
    int r = g_roff[i] + ex[i >> 10];
    g_roff[i] = r;
    g_cursor[i] = r;
    g_inv[i] = 1.0f / fmaxf((float)g_deg[i], 1.0f);
}

__global__ void k_fill(const int* __restrict__ src, const int* __restrict__ dst, int E) {
    int i = blockIdx.x * 256 + threadIdx.x;
    int E4 = E >> 2;
    if (i < E4) {
        int4 d = *(const int4*)(dst + i * 4);
        int4 s = *(const int4*)(src + i * 4);
        int p0 = atomicAdd(&g_cursor[d.x], 1);
        int p1 = atomicAdd(&g_cursor[d.y], 1);
        int p2 = atomicAdd(&g_cursor[d.z], 1);
        int p3 = atomicAdd(&g_cursor[d.w], 1);
        g_csr[p0] = s.x; g_csr[p1] = s.y; g_csr[p2] = s.z; g_csr[p3] = s.w;
    }
    int t = E4 * 4 + i;
    if (t < E) {
        int p = atomicAdd(&g_cursor[dst[t]], 1);
        g_csr[p] = src[t];
    }
}

// ---------------- merged conversions: weights (fp16 images) + x (fp16) ----------------
__global__ void k_conv_all(const float* __restrict__ ws0, const float* __restrict__ wn0,
                           const float* __restrict__ ws1, const float* __restrict__ wn1,
                           const float* __restrict__ ws2, const float* __restrict__ wn2,
                           const float* __restrict__ x, int total4) {
    int idx = blockIdx.x * 256 + threadIdx.x;
    if (idx < 81920) {
        int NOUT;
        const float *ws, *wn;
        __half* img;
        if (idx < 32768) { NOUT = 256; ws = ws0; wn = wn0; img = g_wpad[0]; }
        else if (idx < 65536) { idx -= 32768; NOUT = 256; ws = ws1; wn = wn1; img = g_wpad[1]; }
        else { idx -= 65536; NOUT = 128; ws = ws2; wn = wn2; img = g_wpad[2]; }
        const int HALF = NOUT / 2;
        int nrow = idx / K_DIM, k = idx % K_DIM;
        float v = (nrow < HALF) ? ws[k * HALF + nrow] : wn[k * HALF + (nrow - HALF)];
        img[nrow * WST + k] = __float2half(v);
    } else {
        int i = idx - 81920;
        if (i >= total4) return;
        float4 v = *(const float4*)(x + (size_t)i * 4);
        *(uint2*)(g_ah + (size_t)i * 4) =
            make_uint2(pack_hf2(v.x, v.y), pack_hf2(v.z, v.w));
    }
}

// ---------------- column-split persistent GEMM, fp16 single-pass, 3 CTA/SM ----------------
// grid = 296: cg = bid&1 selects output-column half (0 -> hs fp32, 1 -> hn fp16).
// Processes tiles [tile_begin, tile_end) with stride 148.
template <int NOUT>
__global__ void __launch_bounds__(256, 3)
k_gemm_mma(const __half* __restrict__ Ah,
           const __half* __restrict__ Wimg, float* __restrict__ hs,
           __half* __restrict__ hn, int nrows, int tile_begin, int tile_end) {
    constexpr int HALFN = NOUT / 2;
    constexpr int ABYTES = MT * WST * 2;      // 17408 per A buffer
    constexpr int OFF_W = 2 * ABYTES;
    constexpr int TILES = HALFN / 16;
    extern __shared__ __align__(16) uint8_t smem[];

    const int tid = threadIdx.x;
    const int cg = blockIdx.x & 1;
    const int stride = gridDim.x >> 1;
    const int t0 = tile_begin + (blockIdx.x >> 1);
    const uint32_t sb = smem_u32(smem);

    // ---- stage W half once ----
    for (int i = tid; i < HALFN * 17; i += 256) {
        int r = i / 17, c = i - r * 17;
        const uint8_t* gp =
            (const uint8_t*)(Wimg + (size_t)(cg * HALFN + r) * WST) + c * 16;
        *(uint4*)(smem + OFF_W + r * (WST * 2) + c * 16) = *(const uint4*)gp;
    }

    auto stageA = [&](int tile, int buf) {
        const int m0 = tile * MT;
        const uint32_t base = sb + buf * ABYTES;
        for (int i = tid; i < 1024; i += 256) {
            int r = i >> 4;
            int c = i & 15;
            int row = m0 + r;
            const __half* gp = Ah + (size_t)row * K_DIM + c * 8;
            cp_async16(base + r * (WST * 2) + c * 16, gp,
                       (row < nrows) ? 16 : 0);
        }
        asm volatile("cp.async.commit_group;" ::: "memory");
    };

    const int wid = tid >> 5, lane = tid & 31;
    const int qid = lane >> 2, tig = lane & 3;
    const int rwarp = (wid & 3) * 16;
    const int colsub = (wid >> 2) * (HALFN / 2);

    const int arow = rwarp + (lane & 15);
    const uint32_t aaddr = sb + (uint32_t)arow * (WST * 2) + ((uint32_t)(lane >> 4) << 4);
    const int nrl = colsub + (lane & 7) + ((lane >> 4) << 3);
    const uint32_t bbase = sb + OFF_W + (uint32_t)nrl * (WST * 2) +
                           ((uint32_t)((lane >> 3) & 1) << 4);

    if (t0 < tile_end) stageA(t0, 0);
    int cur = 0;
    for (int tile = t0; tile < tile_end; tile += stride) {
        int nxt = tile + stride;
        if (nxt < tile_end) {
            stageA(nxt, cur ^ 1);
            asm volatile("cp.async.wait_group 1;" ::: "memory");
        } else {
            asm volatile("cp.async.wait_group 0;" ::: "memory");
        }
        __syncthreads();

        float acc[TILES][4];
#pragma unroll
        for (int t = 0; t < TILES; t++)
#pragma unroll
            for (int q = 0; q < 4; q++) acc[t][q] = 0.f;

        const uint32_t aP = aaddr + cur * ABYTES;

#pragma unroll 4
        for (int k0 = 0; k0 < K_DIM; k0 += 16) {
            uint32_t a0, a1, a2, a3;
            ldsm_x4(a0, a1, a2, a3, aP + k0 * 2);
#pragma unroll
            for (int tp = 0; tp < TILES / 2; tp++) {
                const uint32_t boff = tp * (16 * WST * 2) + k0 * 2;
                uint32_t w0, w1, w2, w3;
                ldsm_x4(w0, w1, w2, w3, bbase + boff);
                mma_f16(acc[2 * tp + 0], a0, a1, a2, a3, w0, w1);
                mma_f16(acc[2 * tp + 1], a0, a1, a2, a3, w2, w3);
            }
        }

        const int r0 = tile * MT + rwarp + qid;
        const bool ok0 = r0 < nrows, ok1 = (r0 + 8) < nrows;
        if (cg == 0) {
#pragma unroll
            for (int t = 0; t < TILES; t++) {
                int col = colsub + t * 8 + tig * 2;
                if (ok0) *(float2*)&hs[(size_t)r0 * HALFN + col] = make_float2(acc[t][0], acc[t][1]);
                if (ok1) *(float2*)&hs[(size_t)(r0 + 8) * HALFN + col] = make_float2(acc[t][2], acc[t][3]);
            }
        } else {
#pragma unroll
            for (int t = 0; t < TILES; t++) {
                int col = colsub + t * 8 + tig * 2;
                if (ok0) *(uint32_t*)&hn[(size_t)r0 * HALFN + col] = pack_hf2(acc[t][0], acc[t][1]);
                if (ok1) *(uint32_t*)&hn[(size_t)(r0 + 8) * HALFN + col] = pack_hf2(acc[t][2], acc[t][3]);
            }
        }
        __syncthreads();
        cur ^= 1;
    }
}

// ---------------- aggregation: warp per node, 8-wide MLP, chunked ----------------
// handles nodes [node_off, node_off + cnt)
template <int W, int MODE>
__global__ void k_agg(const float* __restrict__ hs, const __half* __restrict__ hn,
                      const float* __restrict__ bias, float* __restrict__ outf,
                      int node_off, int cnt) {
    constexpr int V = W / 32;
    int wi = (blockIdx.x * blockDim.x + threadIdx.x) >> 5;
    if (wi >= cnt) return;
    int w = node_off + wi;
    int lane = threadIdx.x & 31;

    float acc[V];
#pragma unroll
    for (int c = 0; c < V; c++) acc[c] = 0.f;

    const int start = g_roff[w];
    const int d = g_deg[w];
    const int* __restrict__ cp = g_csr + start;
    int t = 0;
#pragma unroll 1
    for (; t + 8 <= d; t += 8) {
        int j[8];
#pragma unroll
        for (int q = 0; q < 8; q++) j[q] = __ldg(cp + t + q);
        float v[8][V];
#pragma unroll
        for (int q = 0; q < 8; q++)
            hload<V>(v[q], &hn[(size_t)j[q] * W + lane * V]);
#pragma unroll
        for (int q = 0; q < 8; q++)
#pragma unroll
            for (int c = 0; c < V; c++) acc[c] += v[q][c];
    }
    if (t + 4 <= d) {
        int j[4];
#pragma unroll
        for (int q = 0; q < 4; q++) j[q] = __ldg(cp + t + q);
        float v[4][V];
#pragma unroll
        for (int q = 0; q < 4; q++)
            hload<V>(v[q], &hn[(size_t)j[q] * W + lane * V]);
#pragma unroll
        for (int q = 0; q < 4; q++)
#pragma unroll
            for (int c = 0; c < V; c++) acc[c] += v[q][c];
        t += 4;
    }
    for (; t < d; t++) {
        int jj = __ldg(cp + t);
        float vv[V];
        hload<V>(vv, &hn[(size_t)jj * W + lane * V]);
#pragma unroll
        for (int c = 0; c < V; c++) acc[c] += vv[c];
    }

    float inv = g_inv[w];
    float sf[V], bb[V], o[V];
    vload<V>(sf, &hs[(size_t)w * W + lane * V]);
    vload<V>(bb, &bias[lane * V]);
#pragma unroll
    for (int c = 0; c < V; c++) {
        float v = fmaf(inv, acc[c], sf[c]) + bb[c];
        o[c] = (MODE == 1) ? fmaxf(v, 0.f) : v;
    }
    if constexpr (MODE == 1) {
        *(uint2*)(g_ah + (size_t)w * W + lane * V) =
            make_uint2(pack_hf2(o[0], o[1]), pack_hf2(o[2], o[3]));
    } else {
        if constexpr (V == 4)
            *(float4*)(outf + (size_t)w * W + lane * V) = make_float4(o[0], o[1], o[2], o[3]);
        else
            *(float2*)(outf + (size_t)w * W + lane * V) = make_float2(o[0], o[1]);
    }
}

// ---------------------------------------------------------------------------
extern "C" void kernel_launch(void* const* d_in, const int* in_sizes, int n_in,
                              void* d_out, int out_size) {
    const float* x   = (const float*)d_in[0];
    const int*   src = (const int*)d_in[1];
    const int*   dst = (const int*)d_in[2];
    const float* ws0 = (const float*)d_in[3];
    const float* wn0 = (const float*)d_in[4];
    const float* b0  = (const float*)d_in[5];
    const float* ws1 = (const float*)d_in[6];
    const float* wn1 = (const float*)d_in[7];
    const float* b1  = (const float*)d_in[8];
    const float* ws2 = (const float*)d_in[9];
    const float* wn2 = (const float*)d_in[10];
    const float* b2  = (const float*)d_in[11];

    const int n = in_sizes[0] / K_DIM;
    const int E = in_sizes[1];

    void *p_deg, *p_hs, *p_hn, *p_ah, *p_w;
    cudaGetSymbolAddress(&p_deg, g_deg);
    cudaGetSymbolAddress(&p_hs, g_hs);
    cudaGetSymbolAddress(&p_hn, g_hn);
    cudaGetSymbolAddress(&p_ah, g_ah);
    cudaGetSymbolAddress(&p_w, g_wpad);
    float* hs = (float*)p_hs;
    __half* hn = (__half*)p_hn;
    const __half* ah = (const __half*)p_ah;
    __half* wimg = (__half*)p_w;
    constexpr size_t WSLOT = WPART;

    static cudaStream_t s2 = nullptr;
    static cudaEvent_t evF, evG0, evA0, evA1, evG1, evB0, evB1;
    if (!s2) {
        cudaStreamCreateWithFlags(&s2, cudaStreamNonBlocking);
        cudaEventCreateWithFlags(&evF, cudaEventDisableTiming);
        cudaEventCreateWithFlags(&evG0, cudaEventDisableTiming);
        cudaEventCreateWithFlags(&evA0, cudaEventDisableTiming);
        cudaEventCreateWithFlags(&evA1, cudaEventDisableTiming);
        cudaEventCreateWithFlags(&evG1, cudaEventDisableTiming);
        cudaEventCreateWithFlags(&evB0, cudaEventDisableTiming);
        cudaEventCreateWithFlags(&evB1, cudaEventDisableTiming);
    }

    constexpr int ABYTES = MT * WST * 2;
    constexpr int SMEM256 = 2 * ABYTES + 128 * WST * 2;  // 69632
    constexpr int SMEM128 = 2 * ABYTES + 64 * WST * 2;   // 52224
    cudaFuncSetAttribute(k_gemm_mma<256>, cudaFuncAttributeMaxDynamicSharedMemorySize, SMEM256);
    cudaFuncSetAttribute(k_gemm_mma<128>, cudaFuncAttributeMaxDynamicSharedMemorySize, SMEM128);

    const int ntiles = (n + MT - 1) / MT;
    const int gemm_grid = 296;
    const int eb = (E / 4 + 255) / 256;
    const int nb1 = (n + 1023) / 1024;
    const int total4 = n * (K_DIM / 4);
    const int conv_total = 81920 + total4;

    // chunking (2 chunks, tile-aligned)
    const int chT = (ntiles + 1) / 2;          // tiles in chunk 0
    const int c0n = (chT * MT < n) ? chT * MT : n;   // nodes in chunk 0
    const int c1n = n - c0n;
    const int ab0 = (c0n + 7) / 8;
    const int ab1 = (c1n + 7) / 8;
    const int abA = (n + 7) / 8;

    // ---- fork: CSR build on s2, concurrent with conversions + gemm0 ----
    cudaEventRecord(evF, 0);
    cudaStreamWaitEvent(s2, evF, 0);
    cudaMemsetAsync(p_deg, 0, n * sizeof(int), s2);
    k_count<<<eb, 256, 0, s2>>>(dst, E);
    k_scan1<<<nb1, 256, 0, s2>>>(n);
    k_scan23<<<(n + 255) / 256, 256, 0, s2>>>(n, nb1);
    k_fill<<<eb, 256, 0, s2>>>(src, dst, E);

    // main stream: merged conversions, layer-0 GEMM (all tiles)
    k_conv_all<<<(conv_total + 255) / 256, 256>>>(ws0, wn0, ws1, wn1, ws2, wn2, x, total4);
    k_gemm_mma<256><<<gemm_grid, 256, SMEM256>>>(ah, wimg + 0 * WSLOT, hs, hn, n, 0, ntiles);
    cudaEventRecord(evG0, 0);

    // ---- agg0 chunks on s2 (after CSR [same stream] + gemm0 [event]) ----
    cudaStreamWaitEvent(s2, evG0, 0);
    k_agg<128, 1><<<ab0, 256, 0, s2>>>(hs, hn, b0, nullptr, 0, c0n);
    cudaEventRecord(evA0, s2);
    if (c1n > 0) k_agg<128, 1><<<ab1, 256, 0, s2>>>(hs, hn, b0, nullptr, c0n, c1n);
    cudaEventRecord(evA1, s2);

    // ---- gemm1 chunks on main, trailing agg0 chunks ----
    cudaStreamWaitEvent(0, evA0, 0);
    k_gemm_mma<256><<<gemm_grid, 256, SMEM256>>>(ah, wimg + 1 * WSLOT, hs, hn, n, 0, chT);
    cudaStreamWaitEvent(0, evA1, 0);
    k_gemm_mma<256><<<gemm_grid, 256, SMEM256>>>(ah, wimg + 1 * WSLOT, hs, hn, n, chT, ntiles);
    cudaEventRecord(evG1, 0);

    // ---- agg1 chunks on s2 ----
    cudaStreamWaitEvent(s2, evG1, 0);
    k_agg<128, 1><<<ab0, 256, 0, s2>>>(hs, hn, b1, nullptr, 0, c0n);
    cudaEventRecord(evB0, s2);
    if (c1n > 0) k_agg<128, 1><<<ab1, 256, 0, s2>>>(hs, hn, b1, nullptr, c0n, c1n);
    cudaEventRecord(evB1, s2);

    // ---- gemm2 chunks on main, trailing agg1 chunks ----
    cudaStreamWaitEvent(0, evB0, 0);
    k_gemm_mma<128><<<gemm_grid, 256, SMEM128>>>(ah, wimg + 2 * WSLOT, hs, hn, n, 0, chT);
    cudaStreamWaitEvent(0, evB1, 0);
    k_gemm_mma<128><<<gemm_grid, 256, SMEM128>>>(ah, wimg + 2 * WSLOT, hs, hn, n, chT, ntiles);

    // ---- final aggregation (all nodes, fp32 out; ordered after gemm2 on main) ----
    k_agg<64, 0><<<abA, 256>>>(hs, hn, b2, (float*)d_out, 0, n);
}

// round 15
// speedup vs baseline: 1.0693x; 1.0693x over previous
#include <cuda_runtime.h>
#include <cuda_bf16.h>
#include <cuda_fp16.h>
#include <cstdint>

// ---------------------------------------------------------------------------
// GraphSAGE 3-layer forward, GB300 sm_103a (compute_103 PTX -> mma.sync/HMMA).
//   layer: out = h @ Ws + (segmean_dst h[src]) @ Wn + b  (+relu layers 0,1)
// R15 = R13 revert (R14 chunked pipeline regressed) + CSR MLP 4->8:
//   - k_count / k_fill process 8 edges/thread (two int4 loads, 8 atomics in
//     flight) -> atomic latency halved on the forked CSR branch
//   Core (R13): single-pass fp16 GEMM @ 3 CTA/SM, column-split persistent,
//   cp.async double-buffer, vectorized CSR on forked stream, 8-MLP agg.
// ---------------------------------------------------------------------------

#define DINL __device__ __forceinline__

constexpr int NODES_MAX = 100000;
constexpr int EDGES_MAX = 1600000;
constexpr int K_DIM = 128;
constexpr int WST = 136;                 // padded stride (fp16 elems) = 272B
constexpr int WPART = 256 * WST;         // weight image stride (elems)
constexpr int MT = 64;                   // GEMM row-tile

// scratch (__device__ globals; no allocs allowed)
__device__ int   g_deg[NODES_MAX];
__device__ int   g_roff[NODES_MAX];
__device__ int   g_cursor[NODES_MAX];
__device__ int   g_bsums[256];
__device__ int   g_csr[EDGES_MAX];
__device__ float g_inv[NODES_MAX];
__device__ __align__(16) float g_hs[(size_t)NODES_MAX * 128];
__device__ __align__(16) __half g_hn[(size_t)NODES_MAX * 128];
__device__ __align__(16) __half g_ah[(size_t)NODES_MAX * 128];
// per layer: single fp16 part = [N up to 256][WST] (N-major)
__device__ __align__(16) __half g_wpad[3][WPART];

// ---------------- helpers ----------------
DINL uint32_t smem_u32(const void* p) {
    uint32_t a;
    asm("{ .reg .u64 t; cvta.to.shared.u64 t, %1; cvt.u32.u64 %0, t; }"
        : "=r"(a) : "l"(p));
    return a;
}
DINL uint32_t pack_hf2(float a, float b) {
    __half2 t = __floats2half2_rn(a, b);
    return *(uint32_t*)&t;
}
DINL float2 hf2f(uint32_t u) {
    __half2 h = *reinterpret_cast<__half2*>(&u);
    return __half22float2(h);
}
DINL void mma_f16(float (&d)[4], uint32_t a0, uint32_t a1, uint32_t a2, uint32_t a3,
                  uint32_t b0, uint32_t b1) {
    asm volatile(
        "mma.sync.aligned.m16n8k16.row.col.f32.f16.f16.f32 "
        "{%0,%1,%2,%3}, {%4,%5,%6,%7}, {%8,%9}, {%0,%1,%2,%3};"
        : "+f"(d[0]), "+f"(d[1]), "+f"(d[2]), "+f"(d[3])
        : "r"(a0), "r"(a1), "r"(a2), "r"(a3), "r"(b0), "r"(b1));
}
DINL void ldsm_x4(uint32_t& r0, uint32_t& r1, uint32_t& r2, uint32_t& r3, uint32_t addr) {
    asm volatile("ldmatrix.sync.aligned.m8n8.x4.shared.b16 {%0,%1,%2,%3}, [%4];"
                 : "=r"(r0), "=r"(r1), "=r"(r2), "=r"(r3) : "r"(addr));
}
DINL void cp_async16(uint32_t saddr, const void* gptr, int sz) {
    asm volatile("cp.async.cg.shared.global [%0], [%1], 16, %2;"
                 :: "r"(saddr), "l"(gptr), "r"(sz));
}

template <int V>
DINL void vload(float (&v)[V], const float* p) {
    if constexpr (V == 4) {
        float4 t = *(const float4*)p;
        v[0] = t.x; v[1] = t.y; v[2] = t.z; v[3] = t.w;
    } else {
        float2 t = *(const float2*)p;
        v[0] = t.x; v[1] = t.y;
    }
}
template <int V>
DINL void hload(float (&v)[V], const __half* p) {
    if constexpr (V == 4) {
        uint2 u = *(const uint2*)p;
        float2 x = hf2f(u.x), y = hf2f(u.y);
        v[0] = x.x; v[1] = x.y; v[2] = y.x; v[3] = y.y;
    } else {
        uint32_t u = *(const uint32_t*)p;
        float2 x = hf2f(u);
        v[0] = x.x; v[1] = x.y;
    }
}

// ---------------- CSR build (8 edges/thread, MLP=8) ----------------
__global__ void k_count(const int* __restrict__ dst, int E) {
    int i = blockIdx.x * 256 + threadIdx.x;
    int E8 = E >> 3;
    if (i < E8) {
        int4 d0 = *(const int4*)(dst + i * 8);
        int4 d1 = *(const int4*)(dst + i * 8 + 4);
        atomicAdd(&g_deg[d0.x], 1);
        atomicAdd(&g_deg[d0.y], 1);
        atomicAdd(&g_deg[d0.z], 1);
        atomicAdd(&g_deg[d0.w], 1);
        atomicAdd(&g_deg[d1.x], 1);
        atomicAdd(&g_deg[d1.y], 1);
        atomicAdd(&g_deg[d1.z], 1);
        atomicAdd(&g_deg[d1.w], 1);
    }
    int t = E8 * 8 + i;
    if (t < E) atomicAdd(&g_deg[dst[t]], 1);
}

__global__ void k_scan1(int n) {
    __shared__ int sh[256];
    int t = threadIdx.x;
    int i0 = blockIdx.x * 1024 + t * 4;
    int v0 = (i0 + 0 < n) ? g_deg[i0 + 0] : 0;
    int v1 = (i0 + 1 < n) ? g_deg[i0 + 1] : 0;
    int v2 = (i0 + 2 < n) ? g_deg[i0 + 2] : 0;
    int v3 = (i0 + 3 < n) ? g_deg[i0 + 3] : 0;
    int p1 = v0, p2 = v0 + v1, p3 = p2 + v2, tot = p3 + v3;
    sh[t] = tot;
    __syncthreads();
    int incl = tot;
    for (int off = 1; off < 256; off <<= 1) {
        int x = (t >= off) ? sh[t - off] : 0;
        __syncthreads();
        incl += x;
        sh[t] = incl;
        __syncthreads();
    }
    int ex = incl - tot;
    if (i0 + 0 < n) g_roff[i0 + 0] = ex;
    if (i0 + 1 < n) g_roff[i0 + 1] = ex + p1;
    if (i0 + 2 < n) g_roff[i0 + 2] = ex + p2;
    if (i0 + 3 < n) g_roff[i0 + 3] = ex + p3;
    if (t == 255) g_bsums[blockIdx.x] = incl;
}

// merged scan2+scan3: every block redundantly scans g_bsums (nb <= 256)
__global__ void k_scan23(int n, int nb) {
    __shared__ int sh[256];
    __shared__ int ex[256];
    int t = threadIdx.x;
    int v = (t < nb) ? g_bsums[t] : 0;
    sh[t] = v;
    __syncthreads();
    int incl = v;
    for (int off = 1; off < 256; off <<= 1) {
        int x = (t >= off) ? sh[t - off] : 0;
        __syncthreads();
        incl += x;
        sh[t] = incl;
        __syncthreads();
    }
    ex[t] = incl - v;
    __syncthreads();
    int i = blockIdx.x * 256 + t;
    if (i >= n) return;
    int r = g_roff[i] + ex[i >> 10];
    g_roff[i] = r;
    g_cursor[i] = r;
    g_inv[i] = 1.0f / fmaxf((float)g_deg[i], 1.0f);
}

__global__ void k_fill(const int* __restrict__ src, const int* __restrict__ dst, int E) {
    int i = blockIdx.x * 256 + threadIdx.x;
    int E8 = E >> 3;
    if (i < E8) {
        int4 d0 = *(const int4*)(dst + i * 8);
        int4 d1 = *(const int4*)(dst + i * 8 + 4);
        int4 s0 = *(const int4*)(src + i * 8);
        int4 s1 = *(const int4*)(src + i * 8 + 4);
        int p0 = atomicAdd(&g_cursor[d0.x], 1);
        int p1 = atomicAdd(&g_cursor[d0.y], 1);
        int p2 = atomicAdd(&g_cursor[d0.z], 1);
        int p3 = atomicAdd(&g_cursor[d0.w], 1);
        int p4 = atomicAdd(&g_cursor[d1.x], 1);
        int p5 = atomicAdd(&g_cursor[d1.y], 1);
        int p6 = atomicAdd(&g_cursor[d1.z], 1);
        int p7 = atomicAdd(&g_cursor[d1.w], 1);
        g_csr[p0] = s0.x; g_csr[p1] = s0.y; g_csr[p2] = s0.z; g_csr[p3] = s0.w;
        g_csr[p4] = s1.x; g_csr[p5] = s1.y; g_csr[p6] = s1.z; g_csr[p7] = s1.w;
    }
    int t = E8 * 8 + i;
    if (t < E) {
        int p = atomicAdd(&g_cursor[dst[t]], 1);
        g_csr[p] = src[t];
    }
}

// ---------------- merged conversions: weights (fp16 images) + x (fp16) ----------------
__global__ void k_conv_all(const float* __restrict__ ws0, const float* __restrict__ wn0,
                           const float* __restrict__ ws1, const float* __restrict__ wn1,
                           const float* __restrict__ ws2, const float* __restrict__ wn2,
                           const float* __restrict__ x, int total4) {
    int idx = blockIdx.x * 256 + threadIdx.x;
    if (idx < 81920) {
        int NOUT;
        const float *ws, *wn;
        __half* img;
        if (idx < 32768) { NOUT = 256; ws = ws0; wn = wn0; img = g_wpad[0]; }
        else if (idx < 65536) { idx -= 32768; NOUT = 256; ws = ws1; wn = wn1; img = g_wpad[1]; }
        else { idx -= 65536; NOUT = 128; ws = ws2; wn = wn2; img = g_wpad[2]; }
        const int HALF = NOUT / 2;
        int nrow = idx / K_DIM, k = idx % K_DIM;
        float v = (nrow < HALF) ? ws[k * HALF + nrow] : wn[k * HALF + (nrow - HALF)];
        img[nrow * WST + k] = __float2half(v);
    } else {
        int i = idx - 81920;
        if (i >= total4) return;
        float4 v = *(const float4*)(x + (size_t)i * 4);
        *(uint2*)(g_ah + (size_t)i * 4) =
            make_uint2(pack_hf2(v.x, v.y), pack_hf2(v.z, v.w));
    }
}

// ---------------- column-split persistent GEMM, fp16 single-pass, 3 CTA/SM ----------------
// grid = 296: cg = bid&1 selects output-column half (0 -> hs fp32, 1 -> hn fp16),
// t0 = bid>>1, stride 148. 64-row tiles, 256 threads = 8 warps =
// 4 row-strips(16) x 2 col subgroups of HALFN/2. C = A16 @ W16.
template <int NOUT>
__global__ void __launch_bounds__(256, 3)
k_gemm_mma(const __half* __restrict__ Ah,
           const __half* __restrict__ Wimg, float* __restrict__ hs,
           __half* __restrict__ hn, int nrows, int ntiles) {
    constexpr int HALFN = NOUT / 2;           // output width of each dest
    constexpr int ABYTES = MT * WST * 2;      // 17408 per A buffer
    constexpr int OFF_W = 2 * ABYTES;         // A: 2 bufs x 1 part
    constexpr int TILES = HALFN / 16;         // n8 tiles per warp
    extern __shared__ __align__(16) uint8_t smem[];

    const int tid = threadIdx.x;
    const int cg = blockIdx.x & 1;
    const int stride = gridDim.x >> 1;
    const int t0 = blockIdx.x >> 1;
    const uint32_t sb = smem_u32(smem);

    // ---- stage W half once ----
    for (int i = tid; i < HALFN * 17; i += 256) {
        int r = i / 17, c = i - r * 17;
        const uint8_t* gp =
            (const uint8_t*)(Wimg + (size_t)(cg * HALFN + r) * WST) + c * 16;
        *(uint4*)(smem + OFF_W + r * (WST * 2) + c * 16) = *(const uint4*)gp;
    }

    // ---- async A staging (single fp16 part), 64-row tile ----
    auto stageA = [&](int tile, int buf) {
        const int m0 = tile * MT;
        const uint32_t base = sb + buf * ABYTES;
        for (int i = tid; i < 1024; i += 256) {
            int r = i >> 4;
            int c = i & 15;
            int row = m0 + r;
            const __half* gp = Ah + (size_t)row * K_DIM + c * 8;
            cp_async16(base + r * (WST * 2) + c * 16, gp,
                       (row < nrows) ? 16 : 0);
        }
        asm volatile("cp.async.commit_group;" ::: "memory");
    };

    const int wid = tid >> 5, lane = tid & 31;
    const int qid = lane >> 2, tig = lane & 3;
    const int rwarp = (wid & 3) * 16;
    const int colsub = (wid >> 2) * (HALFN / 2);

    const int arow = rwarp + (lane & 15);
    const uint32_t aaddr = sb + (uint32_t)arow * (WST * 2) + ((uint32_t)(lane >> 4) << 4);
    const int nrl = colsub + (lane & 7) + ((lane >> 4) << 3);
    const uint32_t bbase = sb + OFF_W + (uint32_t)nrl * (WST * 2) +
                           ((uint32_t)((lane >> 3) & 1) << 4);

    if (t0 < ntiles) stageA(t0, 0);
    int cur = 0;
    for (int tile = t0; tile < ntiles; tile += stride) {
        int nxt = tile + stride;
        if (nxt < ntiles) {
            stageA(nxt, cur ^ 1);
            asm volatile("cp.async.wait_group 1;" ::: "memory");
        } else {
            asm volatile("cp.async.wait_group 0;" ::: "memory");
        }
        __syncthreads();

        float acc[TILES][4];
#pragma unroll
        for (int t = 0; t < TILES; t++)
#pragma unroll
            for (int q = 0; q < 4; q++) acc[t][q] = 0.f;

        const uint32_t aP = aaddr + cur * ABYTES;

        // single-pass mainloop: C += A*W per k-step
#pragma unroll 4
        for (int k0 = 0; k0 < K_DIM; k0 += 16) {
            uint32_t a0, a1, a2, a3;
            ldsm_x4(a0, a1, a2, a3, aP + k0 * 2);
#pragma unroll
            for (int tp = 0; tp < TILES / 2; tp++) {
                const uint32_t boff = tp * (16 * WST * 2) + k0 * 2;
                uint32_t w0, w1, w2, w3;
                ldsm_x4(w0, w1, w2, w3, bbase + boff);
                mma_f16(acc[2 * tp + 0], a0, a1, a2, a3, w0, w1);
                mma_f16(acc[2 * tp + 1], a0, a1, a2, a3, w2, w3);
            }
        }

        // epilogue: CTA writes only hs (cg=0) or only hn (cg=1), width HALFN
        const int r0 = tile * MT + rwarp + qid;
        const bool ok0 = r0 < nrows, ok1 = (r0 + 8) < nrows;
        if (cg == 0) {
#pragma unroll
            for (int t = 0; t < TILES; t++) {
                int col = colsub + t * 8 + tig * 2;
                if (ok0) *(float2*)&hs[(size_t)r0 * HALFN + col] = make_float2(acc[t][0], acc[t][1]);
                if (ok1) *(float2*)&hs[(size_t)(r0 + 8) * HALFN + col] = make_float2(acc[t][2], acc[t][3]);
            }
        } else {
#pragma unroll
            for (int t = 0; t < TILES; t++) {
                int col = colsub + t * 8 + tig * 2;
                if (ok0) *(uint32_t*)&hn[(size_t)r0 * HALFN + col] = pack_hf2(acc[t][0], acc[t][1]);
                if (ok1) *(uint32_t*)&hn[(size_t)(r0 + 8) * HALFN + col] = pack_hf2(acc[t][2], acc[t][3]);
            }
        }
        __syncthreads();  // all warps done reading buf before it is re-filled
        cur ^= 1;
    }
}

// ---------------- aggregation: warp per node, 8-wide MLP ----------------
// v = hs[i] + inv_deg[i] * sum_{j in N(i)} hn[j] + b   (hn fp16)
// MODE 1: relu(v) -> fp16 (g_ah);  MODE 0: v -> fp32 out
template <int W, int MODE>
__global__ void k_agg(const float* __restrict__ hs, const __half* __restrict__ hn,
                      const float* __restrict__ bias, float* __restrict__ outf, int n) {
    constexpr int V = W / 32;
    int w = (blockIdx.x * blockDim.x + threadIdx.x) >> 5;
    if (w >= n) return;
    int lane = threadIdx.x & 31;

    float acc[V];
#pragma unroll
    for (int c = 0; c < V; c++) acc[c] = 0.f;

    const int start = g_roff[w];
    const int d = g_deg[w];
    const int* __restrict__ cp = g_csr + start;
    int t = 0;
#pragma unroll 1
    for (; t + 8 <= d; t += 8) {
        int j[8];
#pragma unroll
        for (int q = 0; q < 8; q++) j[q] = __ldg(cp + t + q);
        float v[8][V];
#pragma unroll
        for (int q = 0; q < 8; q++)
            hload<V>(v[q], &hn[(size_t)j[q] * W + lane * V]);
#pragma unroll
        for (int q = 0; q < 8; q++)
#pragma unroll
            for (int c = 0; c < V; c++) acc[c] += v[q][c];
    }
    if (t + 4 <= d) {
        int j[4];
#pragma unroll
        for (int q = 0; q < 4; q++) j[q] = __ldg(cp + t + q);
        float v[4][V];
#pragma unroll
        for (int q = 0; q < 4; q++)
            hload<V>(v[q], &hn[(size_t)j[q] * W + lane * V]);
#pragma unroll
        for (int q = 0; q < 4; q++)
#pragma unroll
            for (int c = 0; c < V; c++) acc[c] += v[q][c];
        t += 4;
    }
    for (; t < d; t++) {
        int jj = __ldg(cp + t);
        float vv[V];
        hload<V>(vv, &hn[(size_t)jj * W + lane * V]);
#pragma unroll
        for (int c = 0; c < V; c++) acc[c] += vv[c];
    }

    float inv = g_inv[w];
    float sf[V], bb[V], o[V];
    vload<V>(sf, &hs[(size_t)w * W + lane * V]);
    vload<V>(bb, &bias[lane * V]);
#pragma unroll
    for (int c = 0; c < V; c++) {
        float v = fmaf(inv, acc[c], sf[c]) + bb[c];
        o[c] = (MODE == 1) ? fmaxf(v, 0.f) : v;
    }
    if constexpr (MODE == 1) {
        *(uint2*)(g_ah + (size_t)w * W + lane * V) =
            make_uint2(pack_hf2(o[0], o[1]), pack_hf2(o[2], o[3]));
    } else {
        if constexpr (V == 4)
            *(float4*)(outf + (size_t)w * W + lane * V) = make_float4(o[0], o[1], o[2], o[3]);
        else
            *(float2*)(outf + (size_t)w * W + lane * V) = make_float2(o[0], o[1]);
    }
}

// ---------------------------------------------------------------------------
extern "C" void kernel_launch(void* const* d_in, const int* in_sizes, int n_in,
                              void* d_out, int out_size) {
    const float* x   = (const float*)d_in[0];
    const int*   src = (const int*)d_in[1];
    const int*   dst = (const int*)d_in[2];
    const float* ws0 = (const float*)d_in[3];
    const float* wn0 = (const float*)d_in[4];
    const float* b0  = (const float*)d_in[5];
    const float* ws1 = (const float*)d_in[6];
    const float* wn1 = (const float*)d_in[7];
    const float* b1  = (const float*)d_in[8];
    const float* ws2 = (const float*)d_in[9];
    const float* wn2 = (const float*)d_in[10];
    const float* b2  = (const float*)d_in[11];

    const int n = in_sizes[0] / K_DIM;
    const int E = in_sizes[1];

    void *p_deg, *p_hs, *p_hn, *p_ah, *p_w;
    cudaGetSymbolAddress(&p_deg, g_deg);
    cudaGetSymbolAddress(&p_hs, g_hs);
    cudaGetSymbolAddress(&p_hn, g_hn);
    cudaGetSymbolAddress(&p_ah, g_ah);
    cudaGetSymbolAddress(&p_w, g_wpad);
    float* hs = (float*)p_hs;
    __half* hn = (__half*)p_hn;
    const __half* ah = (const __half*)p_ah;
    __half* wimg = (__half*)p_w;
    constexpr size_t WSLOT = WPART;

    static cudaStream_t s2 = nullptr;
    static cudaEvent_t evF = nullptr, evJ = nullptr;
    if (!s2) {
        cudaStreamCreateWithFlags(&s2, cudaStreamNonBlocking);
        cudaEventCreateWithFlags(&evF, cudaEventDisableTiming);
        cudaEventCreateWithFlags(&evJ, cudaEventDisableTiming);
    }

    constexpr int ABYTES = MT * WST * 2;
    constexpr int SMEM256 = 2 * ABYTES + 128 * WST * 2;  // 69632
    constexpr int SMEM128 = 2 * ABYTES + 64 * WST * 2;   // 52224
    cudaFuncSetAttribute(k_gemm_mma<256>, cudaFuncAttributeMaxDynamicSharedMemorySize, SMEM256);
    cudaFuncSetAttribute(k_gemm_mma<128>, cudaFuncAttributeMaxDynamicSharedMemorySize, SMEM128);

    const int ntiles = (n + MT - 1) / MT;
    const int gemm_grid = 296;  // 2 col groups x 148
    const int eb = (E / 8 + 255) / 256;
    const int nb1 = (n + 1023) / 1024;
    const int ab = (n + 7) / 8;
    const int total4 = n * (K_DIM / 4);
    const int conv_total = 81920 + total4;

    // ---- fork: CSR build on s2, concurrent with conversions + gemm0 ----
    cudaEventRecord(evF, 0);
    cudaStreamWaitEvent(s2, evF, 0);
    cudaMemsetAsync(p_deg, 0, n * sizeof(int), s2);
    k_count<<<eb, 256, 0, s2>>>(dst, E);
    k_scan1<<<nb1, 256, 0, s2>>>(n);
    k_scan23<<<(n + 255) / 256, 256, 0, s2>>>(n, nb1);
    k_fill<<<eb, 256, 0, s2>>>(src, dst, E);
    cudaEventRecord(evJ, s2);

    // main stream: merged conversions, layer-0 GEMM
    k_conv_all<<<(conv_total + 255) / 256, 256>>>(ws0, wn0, ws1, wn1, ws2, wn2, x, total4);
    k_gemm_mma<256><<<gemm_grid, 256, SMEM256>>>(ah, wimg + 0 * WSLOT, hs, hn, n, ntiles);

    // ---- join: agg0 needs CSR + gemm0 ----
    cudaStreamWaitEvent(0, evJ, 0);
    k_agg<128, 1><<<ab, 256>>>(hs, hn, b0, nullptr, n);
    // layer 1
    k_gemm_mma<256><<<gemm_grid, 256, SMEM256>>>(ah, wimg + 1 * WSLOT, hs, hn, n, ntiles);
    k_agg<128, 1><<<ab, 256>>>(hs, hn, b1, nullptr, n);
    // layer 2 (64-wide halves, no relu, fp32 out)
    k_gemm_mma<128><<<gemm_grid, 256, SMEM128>>>(ah, wimg + 2 * WSLOT, hs, hn, n, ntiles);
    k_agg<64, 0><<<ab, 256>>>(hs, hn, b2, (float*)d_out, n);
}

// round 16
// speedup vs baseline: 1.1077x; 1.0359x over previous
#include <cuda_runtime.h>
#include <cuda_bf16.h>
#include <cuda_fp16.h>
#include <cstdint>

// ---------------------------------------------------------------------------
// GraphSAGE 3-layer forward, GB300 sm_103a (compute_103 PTX -> mma.sync/HMMA).
//   layer: out = h @ Ws + (segmean_dst h[src]) @ Wn + b  (+relu layers 0,1)
// R16 = R13 core + hs stored fp16 (self-term traffic halved, ~150 MB saved
//   across the 3 layers); CSR back to 4-edge version (branch fully hidden).
//   Core: single-pass fp16 GEMM @ 3 CTA/SM, column-split persistent,
//   cp.async double-buffer, CSR on forked stream, 8-MLP warp-per-node agg.
// ---------------------------------------------------------------------------

#define DINL __device__ __forceinline__

constexpr int NODES_MAX = 100000;
constexpr int EDGES_MAX = 1600000;
constexpr int K_DIM = 128;
constexpr int WST = 136;                 // padded stride (fp16 elems) = 272B
constexpr int WPART = 256 * WST;         // weight image stride (elems)
constexpr int MT = 64;                   // GEMM row-tile

// scratch (__device__ globals; no allocs allowed)
__device__ int   g_deg[NODES_MAX];
__device__ int   g_roff[NODES_MAX];
__device__ int   g_cursor[NODES_MAX];
__device__ int   g_bsums[256];
__device__ int   g_csr[EDGES_MAX];
__device__ float g_inv[NODES_MAX];
__device__ __align__(16) __half g_hs[(size_t)NODES_MAX * 128];
__device__ __align__(16) __half g_hn[(size_t)NODES_MAX * 128];
__device__ __align__(16) __half g_ah[(size_t)NODES_MAX * 128];
// per layer: single fp16 part = [N up to 256][WST] (N-major)
__device__ __align__(16) __half g_wpad[3][WPART];

// ---------------- helpers ----------------
DINL uint32_t smem_u32(const void* p) {
    uint32_t a;
    asm("{ .reg .u64 t; cvta.to.shared.u64 t, %1; cvt.u32.u64 %0, t; }"
        : "=r"(a) : "l"(p));
    return a;
}
DINL uint32_t pack_hf2(float a, float b) {
    __half2 t = __floats2half2_rn(a, b);
    return *(uint32_t*)&t;
}
DINL float2 hf2f(uint32_t u) {
    __half2 h = *reinterpret_cast<__half2*>(&u);
    return __half22float2(h);
}
DINL void mma_f16(float (&d)[4], uint32_t a0, uint32_t a1, uint32_t a2, uint32_t a3,
                  uint32_t b0, uint32_t b1) {
    asm volatile(
        "mma.sync.aligned.m16n8k16.row.col.f32.f16.f16.f32 "
        "{%0,%1,%2,%3}, {%4,%5,%6,%7}, {%8,%9}, {%0,%1,%2,%3};"
        : "+f"(d[0]), "+f"(d[1]), "+f"(d[2]), "+f"(d[3])
        : "r"(a0), "r"(a1), "r"(a2), "r"(a3), "r"(b0), "r"(b1));
}
DINL void ldsm_x4(uint32_t& r0, uint32_t& r1, uint32_t& r2, uint32_t& r3, uint32_t addr) {
    asm volatile("ldmatrix.sync.aligned.m8n8.x4.shared.b16 {%0,%1,%2,%3}, [%4];"
                 : "=r"(r0), "=r"(r1), "=r"(r2), "=r"(r3) : "r"(addr));
}
DINL void cp_async16(uint32_t saddr, const void* gptr, int sz) {
    asm volatile("cp.async.cg.shared.global [%0], [%1], 16, %2;"
                 :: "r"(saddr), "l"(gptr), "r"(sz));
}

template <int V>
DINL void vload(float (&v)[V], const float* p) {
    if constexpr (V == 4) {
        float4 t = *(const float4*)p;
        v[0] = t.x; v[1] = t.y; v[2] = t.z; v[3] = t.w;
    } else {
        float2 t = *(const float2*)p;
        v[0] = t.x; v[1] = t.y;
    }
}
template <int V>
DINL void hload(float (&v)[V], const __half* p) {
    if constexpr (V == 4) {
        uint2 u = *(const uint2*)p;
        float2 x = hf2f(u.x), y = hf2f(u.y);
        v[0] = x.x; v[1] = x.y; v[2] = y.x; v[3] = y.y;
    } else {
        uint32_t u = *(const uint32_t*)p;
        float2 x = hf2f(u);
        v[0] = x.x; v[1] = x.y;
    }
}

// ---------------- CSR build (4 edges/thread) ----------------
__global__ void k_count(const int* __restrict__ dst, int E) {
    int i = blockIdx.x * 256 + threadIdx.x;
    int E4 = E >> 2;
    if (i < E4) {
        int4 d = *(const int4*)(dst + i * 4);
        atomicAdd(&g_deg[d.x], 1);
        atomicAdd(&g_deg[d.y], 1);
        atomicAdd(&g_deg[d.z], 1);
        atomicAdd(&g_deg[d.w], 1);
    }
    int t = E4 * 4 + i;
    if (t < E) atomicAdd(&g_deg[dst[t]], 1);
}

__global__ void k_scan1(int n) {
    __shared__ int sh[256];
    int t = threadIdx.x;
    int i0 = blockIdx.x * 1024 + t * 4;
    int v0 = (i0 + 0 < n) ? g_deg[i0 + 0] : 0;
    int v1 = (i0 + 1 < n) ? g_deg[i0 + 1] : 0;
    int v2 = (i0 + 2 < n) ? g_deg[i0 + 2] : 0;
    int v3 = (i0 + 3 < n) ? g_deg[i0 + 3] : 0;
    int p1 = v0, p2 = v0 + v1, p3 = p2 + v2, tot = p3 + v3;
    sh[t] = tot;
    __syncthreads();
    int incl = tot;
    for (int off = 1; off < 256; off <<= 1) {
        int x = (t >= off) ? sh[t - off] : 0;
        __syncthreads();
        incl += x;
        sh[t] = incl;
        __syncthreads();
    }
    int ex = incl - tot;
    if (i0 + 0 < n) g_roff[i0 + 0] = ex;
    if (i0 + 1 < n) g_roff[i0 + 1] = ex + p1;
    if (i0 + 2 < n) g_roff[i0 + 2] = ex + p2;
    if (i0 + 3 < n) g_roff[i0 + 3] = ex + p3;
    if (t == 255) g_bsums[blockIdx.x] = incl;
}

// merged scan2+scan3: every block redundantly scans g_bsums (nb <= 256)
__global__ void k_scan23(int n, int nb) {
    __shared__ int sh[256];
    __shared__ int ex[256];
    int t = threadIdx.x;
    int v = (t < nb) ? g_bsums[t] : 0;
    sh[t] = v;
    __syncthreads();
    int incl = v;
    for (int off = 1; off < 256; off <<= 1) {
        int x = (t >= off) ? sh[t - off] : 0;
        __syncthreads();
        incl += x;
        sh[t] = incl;
        __syncthreads();
    }
    ex[t] = incl - v;
    __syncthreads();
    int i = blockIdx.x * 256 + t;
    if (i >= n) return;
    int r = g_roff[i] + ex[i >> 10];
    g_roff[i] = r;
    g_cursor[i] = r;
    g_inv[i] = 1.0f / fmaxf((float)g_deg[i], 1.0f);
}

__global__ void k_fill(const int* __restrict__ src, const int* __restrict__ dst, int E) {
    int i = blockIdx.x * 256 + threadIdx.x;
    int E4 = E >> 2;
    if (i < E4) {
        int4 d = *(const int4*)(dst + i * 4);
        int4 s = *(const int4*)(src + i * 4);
        int p0 = atomicAdd(&g_cursor[d.x], 1);
        int p1 = atomicAdd(&g_cursor[d.y], 1);
        int p2 = atomicAdd(&g_cursor[d.z], 1);
        int p3 = atomicAdd(&g_cursor[d.w], 1);
        g_csr[p0] = s.x; g_csr[p1] = s.y; g_csr[p2] = s.z; g_csr[p3] = s.w;
    }
    int t = E4 * 4 + i;
    if (t < E) {
        int p = atomicAdd(&g_cursor[dst[t]], 1);
        g_csr[p] = src[t];
    }
}

// ---------------- merged conversions: weights (fp16 images) + x (fp16) ----------------
__global__ void k_conv_all(const float* __restrict__ ws0, const float* __restrict__ wn0,
                           const float* __restrict__ ws1, const float* __restrict__ wn1,
                           const float* __restrict__ ws2, const float* __restrict__ wn2,
                           const float* __restrict__ x, int total4) {
    int idx = blockIdx.x * 256 + threadIdx.x;
    if (idx < 81920) {
        int NOUT;
        const float *ws, *wn;
        __half* img;
        if (idx < 32768) { NOUT = 256; ws = ws0; wn = wn0; img = g_wpad[0]; }
        else if (idx < 65536) { idx -= 32768; NOUT = 256; ws = ws1; wn = wn1; img = g_wpad[1]; }
        else { idx -= 65536; NOUT = 128; ws = ws2; wn = wn2; img = g_wpad[2]; }
        const int HALF = NOUT / 2;
        int nrow = idx / K_DIM, k = idx % K_DIM;
        float v = (nrow < HALF) ? ws[k * HALF + nrow] : wn[k * HALF + (nrow - HALF)];
        img[nrow * WST + k] = __float2half(v);
    } else {
        int i = idx - 81920;
        if (i >= total4) return;
        float4 v = *(const float4*)(x + (size_t)i * 4);
        *(uint2*)(g_ah + (size_t)i * 4) =
            make_uint2(pack_hf2(v.x, v.y), pack_hf2(v.z, v.w));
    }
}

// ---------------- column-split persistent GEMM, fp16 single-pass, 3 CTA/SM ----------------
// grid = 296: cg = bid&1 selects output-column half (0 -> hs, 1 -> hn, both fp16),
// t0 = bid>>1, stride 148. 64-row tiles, 256 threads = 8 warps =
// 4 row-strips(16) x 2 col subgroups of HALFN/2. C = A16 @ W16.
template <int NOUT>
__global__ void __launch_bounds__(256, 3)
k_gemm_mma(const __half* __restrict__ Ah,
           const __half* __restrict__ Wimg, __half* __restrict__ hs,
           __half* __restrict__ hn, int nrows, int ntiles) {
    constexpr int HALFN = NOUT / 2;           // output width of each dest
    constexpr int ABYTES = MT * WST * 2;      // 17408 per A buffer
    constexpr int OFF_W = 2 * ABYTES;         // A: 2 bufs x 1 part
    constexpr int TILES = HALFN / 16;         // n8 tiles per warp
    extern __shared__ __align__(16) uint8_t smem[];

    const int tid = threadIdx.x;
    const int cg = blockIdx.x & 1;
    const int stride = gridDim.x >> 1;
    const int t0 = blockIdx.x >> 1;
    const uint32_t sb = smem_u32(smem);

    // ---- stage W half once ----
    for (int i = tid; i < HALFN * 17; i += 256) {
        int r = i / 17, c = i - r * 17;
        const uint8_t* gp =
            (const uint8_t*)(Wimg + (size_t)(cg * HALFN + r) * WST) + c * 16;
        *(uint4*)(smem + OFF_W + r * (WST * 2) + c * 16) = *(const uint4*)gp;
    }

    // ---- async A staging (single fp16 part), 64-row tile ----
    auto stageA = [&](int tile, int buf) {
        const int m0 = tile * MT;
        const uint32_t base = sb + buf * ABYTES;
        for (int i = tid; i < 1024; i += 256) {
            int r = i >> 4;
            int c = i & 15;
            int row = m0 + r;
            const __half* gp = Ah + (size_t)row * K_DIM + c * 8;
            cp_async16(base + r * (WST * 2) + c * 16, gp,
                       (row < nrows) ? 16 : 0);
        }
        asm volatile("cp.async.commit_group;" ::: "memory");
    };

    const int wid = tid >> 5, lane = tid & 31;
    const int qid = lane >> 2, tig = lane & 3;
    const int rwarp = (wid & 3) * 16;
    const int colsub = (wid >> 2) * (HALFN / 2);

    const int arow = rwarp + (lane & 15);
    const uint32_t aaddr = sb + (uint32_t)arow * (WST * 2) + ((uint32_t)(lane >> 4) << 4);
    const int nrl = colsub + (lane & 7) + ((lane >> 4) << 3);
    const uint32_t bbase = sb + OFF_W + (uint32_t)nrl * (WST * 2) +
                           ((uint32_t)((lane >> 3) & 1) << 4);

    if (t0 < ntiles) stageA(t0, 0);
    int cur = 0;
    for (int tile = t0; tile < ntiles; tile += stride) {
        int nxt = tile + stride;
        if (nxt < ntiles) {
            stageA(nxt, cur ^ 1);
            asm volatile("cp.async.wait_group 1;" ::: "memory");
        } else {
            asm volatile("cp.async.wait_group 0;" ::: "memory");
        }
        __syncthreads();

        float acc[TILES][4];
#pragma unroll
        for (int t = 0; t < TILES; t++)
#pragma unroll
            for (int q = 0; q < 4; q++) acc[t][q] = 0.f;

        const uint32_t aP = aaddr + cur * ABYTES;

        // single-pass mainloop: C += A*W per k-step
#pragma unroll 4
        for (int k0 = 0; k0 < K_DIM; k0 += 16) {
            uint32_t a0, a1, a2, a3;
            ldsm_x4(a0, a1, a2, a3, aP + k0 * 2);
#pragma unroll
            for (int tp = 0; tp < TILES / 2; tp++) {
                const uint32_t boff = tp * (16 * WST * 2) + k0 * 2;
                uint32_t w0, w1, w2, w3;
                ldsm_x4(w0, w1, w2, w3, bbase + boff);
                mma_f16(acc[2 * tp + 0], a0, a1, a2, a3, w0, w1);
                mma_f16(acc[2 * tp + 1], a0, a1, a2, a3, w2, w3);
            }
        }

        // epilogue: CTA writes only hs (cg=0) or only hn (cg=1), both fp16
        const int r0 = tile * MT + rwarp + qid;
        const bool ok0 = r0 < nrows, ok1 = (r0 + 8) < nrows;
        __half* dstp = (cg == 0) ? hs : hn;
#pragma unroll
        for (int t = 0; t < TILES; t++) {
            int col = colsub + t * 8 + tig * 2;
            if (ok0) *(uint32_t*)&dstp[(size_t)r0 * HALFN + col] = pack_hf2(acc[t][0], acc[t][1]);
            if (ok1) *(uint32_t*)&dstp[(size_t)(r0 + 8) * HALFN + col] = pack_hf2(acc[t][2], acc[t][3]);
        }
        __syncthreads();  // all warps done reading buf before it is re-filled
        cur ^= 1;
    }
}

// ---------------- aggregation: warp per node, 8-wide MLP ----------------
// v = hs[i] + inv_deg[i] * sum_{j in N(i)} hn[j] + b   (hs, hn fp16)
// MODE 1: relu(v) -> fp16 (g_ah);  MODE 0: v -> fp32 out
template <int W, int MODE>
__global__ void k_agg(const __half* __restrict__ hs, const __half* __restrict__ hn,
                      const float* __restrict__ bias, float* __restrict__ outf, int n) {
    constexpr int V = W / 32;
    int w = (blockIdx.x * blockDim.x + threadIdx.x) >> 5;
    if (w >= n) return;
    int lane = threadIdx.x & 31;

    float acc[V];
#pragma unroll
    for (int c = 0; c < V; c++) acc[c] = 0.f;

    const int start = g_roff[w];
    const int d = g_deg[w];
    const int* __restrict__ cp = g_csr + start;
    int t = 0;
#pragma unroll 1
    for (; t + 8 <= d; t += 8) {
        int j[8];
#pragma unroll
        for (int q = 0; q < 8; q++) j[q] = __ldg(cp + t + q);
        float v[8][V];
#pragma unroll
        for (int q = 0; q < 8; q++)
            hload<V>(v[q], &hn[(size_t)j[q] * W + lane * V]);
#pragma unroll
        for (int q = 0; q < 8; q++)
#pragma unroll
            for (int c = 0; c < V; c++) acc[c] += v[q][c];
    }
    if (t + 4 <= d) {
        int j[4];
#pragma unroll
        for (int q = 0; q < 4; q++) j[q] = __ldg(cp + t + q);
        float v[4][V];
#pragma unroll
        for (int q = 0; q < 4; q++)
            hload<V>(v[q], &hn[(size_t)j[q] * W + lane * V]);
#pragma unroll
        for (int q = 0; q < 4; q++)
#pragma unroll
            for (int c = 0; c < V; c++) acc[c] += v[q][c];
        t += 4;
    }
    for (; t < d; t++) {
        int jj = __ldg(cp + t);
        float vv[V];
        hload<V>(vv, &hn[(size_t)jj * W + lane * V]);
#pragma unroll
        for (int c = 0; c < V; c++) acc[c] += vv[c];
    }

    float inv = g_inv[w];
    float sf[V], bb[V], o[V];
    hload<V>(sf, &hs[(size_t)w * W + lane * V]);
    vload<V>(bb, &bias[lane * V]);
#pragma unroll
    for (int c = 0; c < V; c++) {
        float v = fmaf(inv, acc[c], sf[c]) + bb[c];
        o[c] = (MODE == 1) ? fmaxf(v, 0.f) : v;
    }
    if constexpr (MODE == 1) {
        *(uint2*)(g_ah + (size_t)w * W + lane * V) =
            make_uint2(pack_hf2(o[0], o[1]), pack_hf2(o[2], o[3]));
    } else {
        if constexpr (V == 4)
            *(float4*)(outf + (size_t)w * W + lane * V) = make_float4(o[0], o[1], o[2], o[3]);
        else
            *(float2*)(outf + (size_t)w * W + lane * V) = make_float2(o[0], o[1]);
    }
}

// ---------------------------------------------------------------------------
extern "C" void kernel_launch(void* const* d_in, const int* in_sizes, int n_in,
                              void* d_out, int out_size) {
    const float* x   = (const float*)d_in[0];
    const int*   src = (const int*)d_in[1];
    const int*   dst = (const int*)d_in[2];
    const float* ws0 = (const float*)d_in[3];
    const float* wn0 = (const float*)d_in[4];
    const float* b0  = (const float*)d_in[5];
    const float* ws1 = (const float*)d_in[6];
    const float* wn1 = (const float*)d_in[7];
    const float* b1  = (const float*)d_in[8];
    const float* ws2 = (const float*)d_in[9];
    const float* wn2 = (const float*)d_in[10];
    const float* b2  = (const float*)d_in[11];

    const int n = in_sizes[0] / K_DIM;
    const int E = in_sizes[1];

    void *p_deg, *p_hs, *p_hn, *p_ah, *p_w;
    cudaGetSymbolAddress(&p_deg, g_deg);
    cudaGetSymbolAddress(&p_hs, g_hs);
    cudaGetSymbolAddress(&p_hn, g_hn);
    cudaGetSymbolAddress(&p_ah, g_ah);
    cudaGetSymbolAddress(&p_w, g_wpad);
    __half* hs = (__half*)p_hs;
    __half* hn = (__half*)p_hn;
    const __half* ah = (const __half*)p_ah;
    __half* wimg = (__half*)p_w;
    constexpr size_t WSLOT = WPART;

    static cudaStream_t s2 = nullptr;
    static cudaEvent_t evF = nullptr, evJ = nullptr;
    if (!s2) {
        cudaStreamCreateWithFlags(&s2, cudaStreamNonBlocking);
        cudaEventCreateWithFlags(&evF, cudaEventDisableTiming);
        cudaEventCreateWithFlags(&evJ, cudaEventDisableTiming);
    }

    constexpr int ABYTES = MT * WST * 2;
    constexpr int SMEM256 = 2 * ABYTES + 128 * WST * 2;  // 69632
    constexpr int SMEM128 = 2 * ABYTES + 64 * WST * 2;   // 52224
    cudaFuncSetAttribute(k_gemm_mma<256>, cudaFuncAttributeMaxDynamicSharedMemorySize, SMEM256);
    cudaFuncSetAttribute(k_gemm_mma<128>, cudaFuncAttributeMaxDynamicSharedMemorySize, SMEM128);

    const int ntiles = (n + MT - 1) / MT;
    const int gemm_grid = 296;  // 2 col groups x 148
    const int eb = (E / 4 + 255) / 256;
    const int nb1 = (n + 1023) / 1024;
    const int ab = (n + 7) / 8;
    const int total4 = n * (K_DIM / 4);
    const int conv_total = 81920 + total4;

    // ---- fork: CSR build on s2, concurrent with conversions + gemm0 ----
    cudaEventRecord(evF, 0);
    cudaStreamWaitEvent(s2, evF, 0);
    cudaMemsetAsync(p_deg, 0, n * sizeof(int), s2);
    k_count<<<eb, 256, 0, s2>>>(dst, E);
    k_scan1<<<nb1, 256, 0, s2>>>(n);
    k_scan23<<<(n + 255) / 256, 256, 0, s2>>>(n, nb1);
    k_fill<<<eb, 256, 0, s2>>>(src, dst, E);
    cudaEventRecord(evJ, s2);

    // main stream: merged conversions, layer-0 GEMM
    k_conv_all<<<(conv_total + 255) / 256, 256>>>(ws0, wn0, ws1, wn1, ws2, wn2, x, total4);
    k_gemm_mma<256><<<gemm_grid, 256, SMEM256>>>(ah, wimg + 0 * WSLOT, hs, hn, n, ntiles);

    // ---- join: agg0 needs CSR + gemm0 ----
    cudaStreamWaitEvent(0, evJ, 0);
    k_agg<128, 1><<<ab, 256>>>(hs, hn, b0, nullptr, n);
    // layer 1
    k_gemm_mma<256><<<gemm_grid, 256, SMEM256>>>(ah, wimg + 1 * WSLOT, hs, hn, n, ntiles);
    k_agg<128, 1><<<ab, 256>>>(hs, hn, b1, nullptr, n);
    // layer 2 (64-wide halves, no relu, fp32 out)
    k_gemm_mma<128><<<gemm_grid, 256, SMEM128>>>(ah, wimg + 2 * WSLOT, hs, hn, n, ntiles);
    k_agg<64, 0><<<ab, 256>>>(hs, hn, b2, (float*)d_out, n);
}